// round 12
// baseline (speedup 1.0000x reference)
#include <cuda_runtime.h>
#include <cuda_fp16.h>
#include <cstdint>

#define N_PEP 20000
#define N_MHC 5000
#define N_TCR 100000
#define EMB 128
#define HID 256
#define E_PM 200000
#define E_MT 400000
#define BATCH 50000
#define MAXD 50000

typedef __half h16;

// ---------------- scratch (device globals) ----------------
__device__ h16 g_mean_pm_s[N_MHC * EMB];
__device__ h16 g_mean_mt1c_s[MAXD * EMB];
__device__ h16 g_mean_mt2c_s[MAXD * HID];
__device__ h16 g_embmhc_s[N_MHC * EMB];
__device__ h16 g_embpep_s[N_PEP * EMB];
__device__ h16 g_etcrc_s[MAXD * EMB];
__device__ h16 g_mhc1_s[N_MHC * HID];
__device__ h16 g_tcr1c_s[MAXD * HID];
__device__ h16 g_wsplit[11][256 * 2 * 256];
__device__ float g_cp[N_PEP * HID];
__device__ float g_cm[N_MHC * HID];
__device__ float g_ctc[MAXD * HID];
__device__ float g_Mp[HID * EMB];
__device__ float g_bp[HID];
__device__ int g_map[N_TCR];
__device__ int g_list[MAXD];
__device__ int g_cnt[1];
__device__ int g_head_pm[N_MHC];
__device__ int g_next_pm[E_PM];
__device__ int g_head_mt[N_TCR];
__device__ int g_next_mt[E_MT];

static inline int divup(int a, int b) { return (a + b - 1) / b; }

__device__ __forceinline__ uint32_t smem_u32(const void* p) {
    uint32_t a;
    asm("{ .reg .u64 t; cvta.to.shared.u64 t, %1; cvt.u32.u64 %0, t; }" : "=r"(a) : "l"(p));
    return a;
}
__device__ __forceinline__ void cp16(uint32_t dst, const void* src, bool pred) {
    int sz = pred ? 16 : 0;
    asm volatile("cp.async.cg.shared.global [%0], [%1], 16, %2;"
                 :: "r"(dst), "l"(src), "r"(sz) : "memory");
}
__device__ __forceinline__ void split2h(float x, h16& hi, h16& lo) {
    hi = __float2half(x);
    lo = __float2half(x - __half2float(hi));
}

// ---------------- topology kernels ----------------
__global__ void init_kernel(int* head_pm, int* head_mt, int* map, int* cnt) {
    int i = blockIdx.x * blockDim.x + threadIdx.x;
    if (i == 0) cnt[0] = 0;
    if (i < N_MHC) head_pm[i] = -1;
    if (i < N_TCR) { head_mt[i] = -1; map[i] = -1; }
}
__global__ void build_edges_kernel(const int* __restrict__ dst, int* head, int* next, int E) {
    int e = blockIdx.x * blockDim.x + threadIdx.x;
    if (e < E) next[e] = atomicExch(&head[dst[e]], e);
}
__global__ void mark_kernel(const int* __restrict__ pack, int* map, int B) {
    int i = blockIdx.x * blockDim.x + threadIdx.x;
    if (i < B) map[pack[i]] = -2;
}
__global__ void compact_kernel(int* map, int* list, int* cnt) {
    int i = blockIdx.x * blockDim.x + threadIdx.x;
    if (i < N_TCR && map[i] == -2) {
        int idx = atomicAdd(cnt, 1);
        list[idx] = i;
        map[i] = idx;
    }
}

// ---------------- mean aggregation over fp16 features -> fp16 output ----------------
template <int K>
__global__ void agg_h_kernel(const int* __restrict__ head, const int* __restrict__ next,
                             const int* __restrict__ srcArr, const h16* __restrict__ feat,
                             h16* __restrict__ outS, int nNodes) {
    int w = (blockIdx.x * blockDim.x + threadIdx.x) >> 5;
    int lane = threadIdx.x & 31;
    if (w >= nNodes) return;
    constexpr int NV = K / 128;
    float2 acc[2 * NV];
#pragma unroll
    for (int v = 0; v < 2 * NV; v++) acc[v] = make_float2(0.f, 0.f);
    int e = head[w];
    int cnt = 0;
    while (e >= 0) {
        int en = __ldg(&next[e]);
        int s = __ldg(&srcArr[e]);
        const uint2* fr = (const uint2*)(feat + (size_t)s * K);
#pragma unroll
        for (int p = 0; p < NV; p++) {
            uint2 v = __ldg(&fr[p * 32 + lane]);
            float2 a = __half22float2(*(__half2*)&v.x);
            float2 b = __half22float2(*(__half2*)&v.y);
            acc[p * 2 + 0].x += a.x; acc[p * 2 + 0].y += a.y;
            acc[p * 2 + 1].x += b.x; acc[p * 2 + 1].y += b.y;
        }
        cnt++;
        e = en;
    }
    float inv = 1.0f / (float)(cnt > 1 ? cnt : 1);
    uint2* o = (uint2*)(outS + (size_t)w * K);
#pragma unroll
    for (int p = 0; p < NV; p++) {
        __half2 h0 = __floats2half2_rn(acc[p * 2 + 0].x * inv, acc[p * 2 + 0].y * inv);
        __half2 h1 = __floats2half2_rn(acc[p * 2 + 1].x * inv, acc[p * 2 + 1].y * inv);
        uint2 v;
        v.x = *(uint32_t*)&h0;
        v.y = *(uint32_t*)&h1;
        o[p * 32 + lane] = v;
    }
}

template <int K>
__global__ void agg_h_compact_kernel(const int* __restrict__ head, const int* __restrict__ next,
                                     const int* __restrict__ srcArr, const h16* __restrict__ feat,
                                     h16* __restrict__ outS, const int* __restrict__ list,
                                     const int* __restrict__ cntp) {
    int w = (blockIdx.x * blockDim.x + threadIdx.x) >> 5;
    int lane = threadIdx.x & 31;
    if (w >= __ldg(cntp)) return;
    int node = __ldg(&list[w]);
    constexpr int NV = K / 128;
    float2 acc[2 * NV];
#pragma unroll
    for (int v = 0; v < 2 * NV; v++) acc[v] = make_float2(0.f, 0.f);
    int e = head[node];
    int cnt = 0;
    while (e >= 0) {
        int en = __ldg(&next[e]);
        int s = __ldg(&srcArr[e]);
        const uint2* fr = (const uint2*)(feat + (size_t)s * K);
#pragma unroll
        for (int p = 0; p < NV; p++) {
            uint2 v = __ldg(&fr[p * 32 + lane]);
            float2 a = __half22float2(*(__half2*)&v.x);
            float2 b = __half22float2(*(__half2*)&v.y);
            acc[p * 2 + 0].x += a.x; acc[p * 2 + 0].y += a.y;
            acc[p * 2 + 1].x += b.x; acc[p * 2 + 1].y += b.y;
        }
        cnt++;
        e = en;
    }
    float inv = 1.0f / (float)(cnt > 1 ? cnt : 1);
    uint2* o = (uint2*)(outS + (size_t)w * K);
#pragma unroll
    for (int p = 0; p < NV; p++) {
        __half2 h0 = __floats2half2_rn(acc[p * 2 + 0].x * inv, acc[p * 2 + 0].y * inv);
        __half2 h1 = __floats2half2_rn(acc[p * 2 + 1].x * inv, acc[p * 2 + 1].y * inv);
        uint2 v;
        v.x = *(uint32_t*)&h0;
        v.y = *(uint32_t*)&h1;
        o[p * 32 + lane] = v;
    }
}

// ---------------- fp32 -> fp16 conversions ----------------
__global__ void conv_h_kernel(const float* __restrict__ src, h16* __restrict__ dst, int n) {
    int i = blockIdx.x * blockDim.x + threadIdx.x;
    if (i < n) dst[i] = __float2half(__ldg(&src[i]));
}

__global__ void gather_conv_h_kernel(const float* __restrict__ src, h16* __restrict__ dst,
                                     const int* __restrict__ list, const int* __restrict__ cntp,
                                     int K) {
    int idx = blockIdx.x * blockDim.x + threadIdx.x;
    int cnt = __ldg(cntp);
    if (idx >= cnt * K) return;
    int r = idx / K, k = idx - r * K;
    int sr = __ldg(&list[r]);
    dst[(size_t)r * K + k] = __float2half(__ldg(&src[(size_t)sr * K + k]));
}

struct WEntry { const float* src; h16* dst; int ld, off, K; };
struct WTable { WEntry e[11]; };
__global__ void wconv_kernel(WTable tab) {
    WEntry w = tab.e[blockIdx.y];
    int idx = blockIdx.x * 256 + threadIdx.x;
    if (idx >= 256 * w.K) return;
    int n = idx / w.K, k = idx - n * w.K;
    h16 hi, lo;
    split2h(__ldg(&w.src[(size_t)n * w.ld + w.off + k]), hi, lo);
    w.dst[((size_t)n * 2) * w.K + k] = hi;
    w.dst[((size_t)n * 2 + 1) * w.K + k] = lo;
}

// ---------------- warp-MMA fp16 GEMM (2-term weight split) + optional fused stage-2 ----------------
#define KC2 32
#define STR2 40
#define YSTR 264
#define SM_Y 0
#define SM_A_OFF(stg)    (67584 + (stg) * 10240)
#define SM_W_OFF(stg, p) (88064 + ((stg) * 2 + (p)) * 20480)
#define SMEM_TOTAL_G (88064 + 81920)

__global__ __launch_bounds__(512) void mma_gemm_kernel(
    const h16* __restrict__ A, int Ka, const h16* __restrict__ Wa,
    const h16* __restrict__ B, int Kb, const h16* __restrict__ Wb,
    const float* __restrict__ bias, const int* __restrict__ rows_ptr, int rows,
    float* __restrict__ Yf, h16* __restrict__ Ys, int do_relu,
    const h16* __restrict__ V, float* __restrict__ Y2f) {
    if (rows_ptr) { int r = __ldg(rows_ptr); if (r < rows) rows = r; }
    const int m0 = blockIdx.x * 128;
    if (m0 >= rows) return;

    extern __shared__ char dynsm[];
    const uint32_t sb = smem_u32(dynsm);

    const int t = threadIdx.x, lane = t & 31, wid = t >> 5;
    const int wm = wid & 1;
    const int wn = wid >> 1;
    const int g = lane >> 2, tg = lane & 3;

    const int a_row = lane & 15;
    const int a_coff = (lane >> 4) << 3;
    const int b_row = lane & 7;
    const int b_coff = ((lane >> 3) & 1) << 3;

    float acc[4][4][4];
#pragma unroll
    for (int i = 0; i < 4; i++)
#pragma unroll
        for (int j = 0; j < 4; j++)
#pragma unroll
            for (int c = 0; c < 4; c++) acc[i][j][c] = 0.f;

    const int nchA = Ka / KC2;
    const int nch = nchA + (B ? Kb / KC2 : 0);

    const int la_row = t >> 2, la_seg = t & 3;
    const bool la_in = (m0 + la_row) < rows;

    auto issue = [&](int c, int stg) {
        const bool isB = (c >= nchA);
        const int k0 = (isB ? c - nchA : c) * KC2;
        const h16* X = isB ? B : A;
        const h16* W = isB ? Wb : Wa;
        const int Kx = isB ? Kb : Ka;
        {
            uint32_t dst = sb + SM_A_OFF(stg) + (la_row * STR2 + la_seg * 8) * 2;
            const h16* src = X + (size_t)(m0 + la_row) * Kx + k0 + la_seg * 8;
            cp16(dst, src, la_in);
        }
#pragma unroll
        for (int p = 0; p < 2; p++) {
#pragma unroll
            for (int rep = 0; rep < 2; rep++) {
                int u = t + rep * 512;
                int wr = u >> 2, ws = u & 3;
                uint32_t dst = sb + SM_W_OFF(stg, p) + (wr * STR2 + ws * 8) * 2;
                const h16* src = W + ((size_t)wr * 2 + p) * Kx + k0 + ws * 8;
                cp16(dst, src, true);
            }
        }
        asm volatile("cp.async.commit_group;" ::: "memory");
    };

    issue(0, 0);
    for (int c = 0; c < nch; c++) {
        const int stg = c & 1;
        if (c + 1 < nch) {
            issue(c + 1, (c + 1) & 1);
            asm volatile("cp.async.wait_group 1;" ::: "memory");
        } else {
            asm volatile("cp.async.wait_group 0;" ::: "memory");
        }
        __syncthreads();

#pragma unroll
        for (int ks = 0; ks < 2; ks++) {
            const int kc = ks * 16;
            uint32_t bh[4][2], bl[4][2];
#pragma unroll
            for (int nt = 0; nt < 4; nt++) {
                int nr = wn * 32 + nt * 8;
                uint32_t off = ((nr + b_row) * STR2 + kc + b_coff) * 2;
                asm volatile("ldmatrix.sync.aligned.m8n8.x2.shared.b16 {%0,%1}, [%2];"
                             : "=r"(bh[nt][0]), "=r"(bh[nt][1])
                             : "r"(sb + SM_W_OFF(stg, 0) + off));
                asm volatile("ldmatrix.sync.aligned.m8n8.x2.shared.b16 {%0,%1}, [%2];"
                             : "=r"(bl[nt][0]), "=r"(bl[nt][1])
                             : "r"(sb + SM_W_OFF(stg, 1) + off));
            }
#pragma unroll
            for (int mt = 0; mt < 4; mt++) {
                int mr = wm * 64 + mt * 16;
                uint32_t ah[4];
                uint32_t pa = sb + SM_A_OFF(stg) + ((mr + a_row) * STR2 + kc + a_coff) * 2;
                asm volatile("ldmatrix.sync.aligned.m8n8.x4.shared.b16 {%0,%1,%2,%3}, [%4];"
                             : "=r"(ah[0]), "=r"(ah[1]), "=r"(ah[2]), "=r"(ah[3]) : "r"(pa));
#pragma unroll
                for (int nt = 0; nt < 4; nt++) {
                    asm volatile(
                        "mma.sync.aligned.m16n8k16.row.col.f32.f16.f16.f32 "
                        "{%0,%1,%2,%3}, {%4,%5,%6,%7}, {%8,%9}, {%0,%1,%2,%3};"
                        : "+f"(acc[mt][nt][0]), "+f"(acc[mt][nt][1]),
                          "+f"(acc[mt][nt][2]), "+f"(acc[mt][nt][3])
                        : "r"(ah[0]), "r"(ah[1]), "r"(ah[2]), "r"(ah[3]),
                          "r"(bh[nt][0]), "r"(bh[nt][1]));
                    asm volatile(
                        "mma.sync.aligned.m16n8k16.row.col.f32.f16.f16.f32 "
                        "{%0,%1,%2,%3}, {%4,%5,%6,%7}, {%8,%9}, {%0,%1,%2,%3};"
                        : "+f"(acc[mt][nt][0]), "+f"(acc[mt][nt][1]),
                          "+f"(acc[mt][nt][2]), "+f"(acc[mt][nt][3])
                        : "r"(ah[0]), "r"(ah[1]), "r"(ah[2]), "r"(ah[3]),
                          "r"(bl[nt][0]), "r"(bl[nt][1]));
                }
            }
        }
        __syncthreads();
    }

    if (!V) {
#pragma unroll
        for (int mt = 0; mt < 4; mt++) {
            int r0 = m0 + wm * 64 + mt * 16 + g;
#pragma unroll
            for (int half = 0; half < 2; half++) {
                int row = r0 + half * 8;
                if (row >= rows) continue;
#pragma unroll
                for (int nt = 0; nt < 4; nt++) {
                    int col = wn * 32 + nt * 8 + tg * 2;
                    float v0 = acc[mt][nt][half * 2 + 0];
                    float v1 = acc[mt][nt][half * 2 + 1];
                    if (bias) { v0 += __ldg(&bias[col]); v1 += __ldg(&bias[col + 1]); }
                    if (do_relu) { v0 = fmaxf(v0, 0.f); v1 = fmaxf(v1, 0.f); }
                    if (Yf) *(float2*)(Yf + (size_t)row * HID + col) = make_float2(v0, v1);
                    if (Ys) *(__half2*)(Ys + (size_t)row * HID + col) = __floats2half2_rn(v0, v1);
                }
            }
        }
        return;
    }

    // ---- fused stage 2: Y2 = T @ V^T ----
    auto issueV = [&](int c, int stg) {
        const int k0 = c * KC2;
#pragma unroll
        for (int p = 0; p < 2; p++) {
#pragma unroll
            for (int rep = 0; rep < 2; rep++) {
                int u = t + rep * 512;
                int wr = u >> 2, ws = u & 3;
                uint32_t dst = sb + SM_W_OFF(stg, p) + (wr * STR2 + ws * 8) * 2;
                const h16* src = V + ((size_t)wr * 2 + p) * HID + k0 + ws * 8;
                cp16(dst, src, true);
            }
        }
        asm volatile("cp.async.commit_group;" ::: "memory");
    };

    // prefetch first V chunk while we spill the stage-1 tile to smem
    issueV(0, 0);

#pragma unroll
    for (int mt = 0; mt < 4; mt++) {
        int lr0 = wm * 64 + mt * 16 + g;
#pragma unroll
        for (int half = 0; half < 2; half++) {
            int lrow = lr0 + half * 8;
#pragma unroll
            for (int nt = 0; nt < 4; nt++) {
                int col = wn * 32 + nt * 8 + tg * 2;
                float v0 = acc[mt][nt][half * 2 + 0];
                float v1 = acc[mt][nt][half * 2 + 1];
                if (bias) { v0 += __ldg(&bias[col]); v1 += __ldg(&bias[col + 1]); }
                if (do_relu) { v0 = fmaxf(v0, 0.f); v1 = fmaxf(v1, 0.f); }
                *(__half2*)(dynsm + SM_Y + (lrow * YSTR + col) * 2) = __floats2half2_rn(v0, v1);
            }
        }
    }

#pragma unroll
    for (int i = 0; i < 4; i++)
#pragma unroll
        for (int j = 0; j < 4; j++)
#pragma unroll
            for (int c = 0; c < 4; c++) acc[i][j][c] = 0.f;

    const int nch2 = HID / KC2;  // 8
    __syncthreads();  // Ysm visible
    for (int c = 0; c < nch2; c++) {
        const int stg = c & 1;
        if (c + 1 < nch2) {
            issueV(c + 1, (c + 1) & 1);
            asm volatile("cp.async.wait_group 1;" ::: "memory");
        } else {
            asm volatile("cp.async.wait_group 0;" ::: "memory");
        }
        __syncthreads();
        const int k0 = c * KC2;

#pragma unroll
        for (int ks = 0; ks < 2; ks++) {
            const int kc = ks * 16;
            uint32_t bh[4][2], bl[4][2];
#pragma unroll
            for (int nt = 0; nt < 4; nt++) {
                int nr = wn * 32 + nt * 8;
                uint32_t off = ((nr + b_row) * STR2 + kc + b_coff) * 2;
                asm volatile("ldmatrix.sync.aligned.m8n8.x2.shared.b16 {%0,%1}, [%2];"
                             : "=r"(bh[nt][0]), "=r"(bh[nt][1])
                             : "r"(sb + SM_W_OFF(stg, 0) + off));
                asm volatile("ldmatrix.sync.aligned.m8n8.x2.shared.b16 {%0,%1}, [%2];"
                             : "=r"(bl[nt][0]), "=r"(bl[nt][1])
                             : "r"(sb + SM_W_OFF(stg, 1) + off));
            }
#pragma unroll
            for (int mt = 0; mt < 4; mt++) {
                int mr = wm * 64 + mt * 16;
                uint32_t ah[4];
                uint32_t pa = sb + SM_Y + ((mr + a_row) * YSTR + k0 + kc + a_coff) * 2;
                asm volatile("ldmatrix.sync.aligned.m8n8.x4.shared.b16 {%0,%1,%2,%3}, [%4];"
                             : "=r"(ah[0]), "=r"(ah[1]), "=r"(ah[2]), "=r"(ah[3]) : "r"(pa));
#pragma unroll
                for (int nt = 0; nt < 4; nt++) {
                    asm volatile(
                        "mma.sync.aligned.m16n8k16.row.col.f32.f16.f16.f32 "
                        "{%0,%1,%2,%3}, {%4,%5,%6,%7}, {%8,%9}, {%0,%1,%2,%3};"
                        : "+f"(acc[mt][nt][0]), "+f"(acc[mt][nt][1]),
                          "+f"(acc[mt][nt][2]), "+f"(acc[mt][nt][3])
                        : "r"(ah[0]), "r"(ah[1]), "r"(ah[2]), "r"(ah[3]),
                          "r"(bh[nt][0]), "r"(bh[nt][1]));
                    asm volatile(
                        "mma.sync.aligned.m16n8k16.row.col.f32.f16.f16.f32 "
                        "{%0,%1,%2,%3}, {%4,%5,%6,%7}, {%8,%9}, {%0,%1,%2,%3};"
                        : "+f"(acc[mt][nt][0]), "+f"(acc[mt][nt][1]),
                          "+f"(acc[mt][nt][2]), "+f"(acc[mt][nt][3])
                        : "r"(ah[0]), "r"(ah[1]), "r"(ah[2]), "r"(ah[3]),
                          "r"(bl[nt][0]), "r"(bl[nt][1]));
                }
            }
        }
        __syncthreads();
    }

#pragma unroll
    for (int mt = 0; mt < 4; mt++) {
        int r0 = m0 + wm * 64 + mt * 16 + g;
#pragma unroll
        for (int half = 0; half < 2; half++) {
            int row = r0 + half * 8;
            if (row >= rows) continue;
#pragma unroll
            for (int nt = 0; nt < 4; nt++) {
                int col = wn * 32 + nt * 8 + tg * 2;
                *(float2*)(Y2f + (size_t)row * HID + col) =
                    make_float2(acc[mt][nt][half * 2 + 0], acc[mt][nt][half * 2 + 1]);
            }
        }
    }
}

// ---------------- head folding precompute ----------------
__global__ void prep_head_kernel(const float* __restrict__ head_W1, const float* __restrict__ head_b1,
                                 const float* __restrict__ proj_W, const float* __restrict__ proj_b,
                                 float* __restrict__ Mp, float* __restrict__ bp) {
    int n = blockIdx.x;
    int k = threadIdx.x;
    float acc = 0.f;
    for (int j = 0; j < HID; j++) {
        float w = __ldg(&head_W1[n * (3 * HID) + j]);
        acc = fmaf(w, __ldg(&proj_W[j * EMB + k]), acc);
    }
    Mp[n * EMB + k] = acc;
    float pb = __ldg(&head_W1[n * (3 * HID) + k]) * __ldg(&proj_b[k]) +
               __ldg(&head_W1[n * (3 * HID) + k + 128]) * __ldg(&proj_b[k + 128]);
    __shared__ float s[128];
    s[k] = pb;
    __syncthreads();
    for (int st = 64; st > 0; st >>= 1) {
        if (k < st) s[k] += s[k + st];
        __syncthreads();
    }
    if (k == 0) bp[n] = s[0] + head_b1[n];
}

// ---------------- final ----------------
__global__ void final_kernel(const int* __restrict__ pp, const int* __restrict__ pm,
                             const int* __restrict__ pt, const int* __restrict__ map,
                             const float* __restrict__ cp, const float* __restrict__ cm,
                             const float* __restrict__ ctc, const float* __restrict__ w2,
                             const float* __restrict__ b2, float* __restrict__ out, int Bn) {
    int w = (blockIdx.x * blockDim.x + threadIdx.x) >> 5;
    int lane = threadIdx.x & 31;
    if (w >= Bn) return;
    int ip = __ldg(&pp[w]);
    int im = __ldg(&pm[w]);
    int it = __ldg(&map[__ldg(&pt[w])]);
    const float4* rp = (const float4*)(cp + (size_t)ip * HID);
    const float4* rm = (const float4*)(cm + (size_t)im * HID);
    const float4* rt = (const float4*)(ctc + (size_t)it * HID);
    const float4* rw = (const float4*)w2;
    float sum = 0.f;
#pragma unroll
    for (int v = 0; v < 2; v++) {
        float4 a = __ldg(&rp[lane + v * 32]);
        float4 b = __ldg(&rm[lane + v * 32]);
        float4 c = __ldg(&rt[lane + v * 32]);
        float4 ww = __ldg(&rw[lane + v * 32]);
        sum = fmaf(fmaxf(a.x + b.x + c.x, 0.f), ww.x, sum);
        sum = fmaf(fmaxf(a.y + b.y + c.y, 0.f), ww.y, sum);
        sum = fmaf(fmaxf(a.z + b.z + c.z, 0.f), ww.z, sum);
        sum = fmaf(fmaxf(a.w + b.w + c.w, 0.f), ww.w, sum);
    }
#pragma unroll
    for (int o = 16; o > 0; o >>= 1) sum += __shfl_xor_sync(0xFFFFFFFFu, sum, o);
    if (lane == 0) out[w] = sum + b2[0];
}

// ---------------- launch ----------------
static void launch_mma_s(cudaStream_t st, const h16* A, int Ka, const h16* Wa, const h16* B,
                         int Kb, const h16* Wb, const float* bias, const int* rows_ptr, int rows,
                         float* Yf, h16* Ys, int relu, const h16* V, float* Y2f) {
    mma_gemm_kernel<<<divup(rows, 128), 512, SMEM_TOTAL_G, st>>>(A, Ka, Wa, B, Kb, Wb, bias,
                                                                 rows_ptr, rows, Yf, Ys, relu,
                                                                 V, Y2f);
}

extern "C" void kernel_launch(void* const* d_in, const int* in_sizes, int n_in,
                              void* d_out, int out_size) {
    const float* emb_pep = (const float*)d_in[0];
    const float* emb_mhc = (const float*)d_in[1];
    const float* emb_tcr = (const float*)d_in[2];
    const int* src_pm = (const int*)d_in[3];
    const int* dst_pm = (const int*)d_in[4];
    const int* src_mt = (const int*)d_in[5];
    const int* dst_mt = (const int*)d_in[6];
    const int* pack_pep = (const int*)d_in[7];
    const int* pack_mhc = (const int*)d_in[8];
    const int* pack_tcr = (const int*)d_in[9];
    const float* l1_pm_Wl = (const float*)d_in[10];
    const float* l1_pm_bl = (const float*)d_in[11];
    const float* l1_pm_Wr = (const float*)d_in[12];
    const float* l1_mt_Wl = (const float*)d_in[13];
    const float* l1_mt_bl = (const float*)d_in[14];
    const float* l1_mt_Wr = (const float*)d_in[15];
    const float* l2_pm_Wl = (const float*)d_in[16];
    const float* l2_pm_bl = (const float*)d_in[17];
    const float* l2_pm_Wr = (const float*)d_in[18];
    const float* l2_mt_Wl = (const float*)d_in[19];
    const float* l2_mt_bl = (const float*)d_in[20];
    const float* l2_mt_Wr = (const float*)d_in[21];
    const float* proj_W = (const float*)d_in[22];
    const float* proj_b = (const float*)d_in[23];
    const float* head_W1 = (const float*)d_in[24];
    const float* head_b1 = (const float*)d_in[25];
    const float* head_W2 = (const float*)d_in[26];
    const float* head_b2 = (const float*)d_in[27];
    float* out = (float*)d_out;

    static cudaStream_t s1 = 0, s2 = 0, s3 = 0;
    static cudaEvent_t eBegin, ePm, eTopo, eEmbPep, eEmbMhc, eWconv, eEtcr, eMhc1, eMt2, eCm, eCp;
    static bool inited = false;
    if (!inited) {
        cudaFuncSetAttribute(mma_gemm_kernel, cudaFuncAttributeMaxDynamicSharedMemorySize,
                             SMEM_TOTAL_G);
        cudaStreamCreateWithFlags(&s1, cudaStreamNonBlocking);
        cudaStreamCreateWithFlags(&s2, cudaStreamNonBlocking);
        cudaStreamCreateWithFlags(&s3, cudaStreamNonBlocking);
        cudaEventCreateWithFlags(&eBegin, cudaEventDisableTiming);
        cudaEventCreateWithFlags(&ePm, cudaEventDisableTiming);
        cudaEventCreateWithFlags(&eTopo, cudaEventDisableTiming);
        cudaEventCreateWithFlags(&eEmbPep, cudaEventDisableTiming);
        cudaEventCreateWithFlags(&eEmbMhc, cudaEventDisableTiming);
        cudaEventCreateWithFlags(&eWconv, cudaEventDisableTiming);
        cudaEventCreateWithFlags(&eEtcr, cudaEventDisableTiming);
        cudaEventCreateWithFlags(&eMhc1, cudaEventDisableTiming);
        cudaEventCreateWithFlags(&eMt2, cudaEventDisableTiming);
        cudaEventCreateWithFlags(&eCm, cudaEventDisableTiming);
        cudaEventCreateWithFlags(&eCp, cudaEventDisableTiming);
        inited = true;
    }
    cudaStream_t s0 = 0;

    h16 *mean_pm_s, *mean_mt1c_s, *mean_mt2c_s, *embmhc_s, *embpep_s, *etcrc_s;
    h16 *mhc1_s, *tcr1c_s, *wsplit;
    float *cp, *cm, *ctc, *Mp, *bp;
    int *map, *list, *cnt, *head_pm, *next_pm, *head_mt, *next_mt;
    cudaGetSymbolAddress((void**)&mean_pm_s, g_mean_pm_s);
    cudaGetSymbolAddress((void**)&mean_mt1c_s, g_mean_mt1c_s);
    cudaGetSymbolAddress((void**)&mean_mt2c_s, g_mean_mt2c_s);
    cudaGetSymbolAddress((void**)&embmhc_s, g_embmhc_s);
    cudaGetSymbolAddress((void**)&embpep_s, g_embpep_s);
    cudaGetSymbolAddress((void**)&etcrc_s, g_etcrc_s);
    cudaGetSymbolAddress((void**)&mhc1_s, g_mhc1_s);
    cudaGetSymbolAddress((void**)&tcr1c_s, g_tcr1c_s);
    cudaGetSymbolAddress((void**)&wsplit, g_wsplit);
    cudaGetSymbolAddress((void**)&cp, g_cp);
    cudaGetSymbolAddress((void**)&cm, g_cm);
    cudaGetSymbolAddress((void**)&ctc, g_ctc);
    cudaGetSymbolAddress((void**)&Mp, g_Mp);
    cudaGetSymbolAddress((void**)&bp, g_bp);
    cudaGetSymbolAddress((void**)&map, g_map);
    cudaGetSymbolAddress((void**)&list, g_list);
    cudaGetSymbolAddress((void**)&cnt, g_cnt);
    cudaGetSymbolAddress((void**)&head_pm, g_head_pm);
    cudaGetSymbolAddress((void**)&next_pm, g_next_pm);
    cudaGetSymbolAddress((void**)&head_mt, g_head_mt);
    cudaGetSymbolAddress((void**)&next_mt, g_next_mt);

    const int WSLOT = 256 * 2 * 256;
    h16* w_l1pmWl = wsplit + 0 * WSLOT;
    h16* w_l1pmWr = wsplit + 1 * WSLOT;
    h16* w_l1mtWl = wsplit + 2 * WSLOT;
    h16* w_l1mtWr = wsplit + 3 * WSLOT;
    h16* w_l2pmWl = wsplit + 4 * WSLOT;
    h16* w_l2pmWr = wsplit + 5 * WSLOT;
    h16* w_l2mtWl = wsplit + 6 * WSLOT;
    h16* w_l2mtWr = wsplit + 7 * WSLOT;
    h16* w_Mp     = wsplit + 8 * WSLOT;
    h16* w_W1m    = wsplit + 9 * WSLOT;
    h16* w_W1t    = wsplit + 10 * WSLOT;

    // ---- fork ----
    cudaEventRecord(eBegin, s0);
    cudaStreamWaitEvent(s1, eBegin, 0);
    cudaStreamWaitEvent(s2, eBegin, 0);
    cudaStreamWaitEvent(s3, eBegin, 0);

    // ---- s0: topology (pm list first so the mhc chain can start early) ----
    init_kernel<<<divup(N_TCR, 256), 256, 0, s0>>>(head_pm, head_mt, map, cnt);
    build_edges_kernel<<<divup(E_PM, 256), 256, 0, s0>>>(dst_pm, head_pm, next_pm, E_PM);
    cudaEventRecord(ePm, s0);
    build_edges_kernel<<<divup(E_MT, 256), 256, 0, s0>>>(dst_mt, head_mt, next_mt, E_MT);
    mark_kernel<<<divup(BATCH, 256), 256, 0, s0>>>(pack_tcr, map, BATCH);
    compact_kernel<<<divup(N_TCR, 256), 256, 0, s0>>>(map, list, cnt);
    cudaEventRecord(eTopo, s0);

    // ---- s2: pep conversion first (agg_pm dependency), then weights + pep branch ----
    conv_h_kernel<<<divup(N_PEP * EMB, 256), 256, 0, s2>>>(emb_pep, embpep_s, N_PEP * EMB);
    cudaEventRecord(eEmbPep, s2);
    prep_head_kernel<<<HID, 128, 0, s2>>>(head_W1, head_b1, proj_W, proj_b, Mp, bp);
    {
        WTable tab;
        tab.e[0] = {l1_pm_Wl, w_l1pmWl, EMB, 0, EMB};
        tab.e[1] = {l1_pm_Wr, w_l1pmWr, EMB, 0, EMB};
        tab.e[2] = {l1_mt_Wl, w_l1mtWl, EMB, 0, EMB};
        tab.e[3] = {l1_mt_Wr, w_l1mtWr, EMB, 0, EMB};
        tab.e[4] = {l2_pm_Wl, w_l2pmWl, EMB, 0, EMB};
        tab.e[5] = {l2_pm_Wr, w_l2pmWr, HID, 0, HID};
        tab.e[6] = {l2_mt_Wl, w_l2mtWl, HID, 0, HID};
        tab.e[7] = {l2_mt_Wr, w_l2mtWr, HID, 0, HID};
        tab.e[8] = {Mp, w_Mp, EMB, 0, EMB};
        tab.e[9] = {head_W1, w_W1m, 3 * HID, HID, HID};
        tab.e[10] = {head_W1, w_W1t, 3 * HID, 2 * HID, HID};
        wconv_kernel<<<dim3(256, 11), 256, 0, s2>>>(tab);
    }
    cudaEventRecord(eWconv, s2);
    cudaStreamWaitEvent(s2, eTopo, 0);
    gather_conv_h_kernel<<<divup(MAXD * EMB, 256), 256, 0, s2>>>(emb_tcr, etcrc_s, list, cnt, EMB);
    cudaEventRecord(eEtcr, s2);
    launch_mma_s(s2, embpep_s, EMB, w_Mp, nullptr, 0, nullptr, bp, nullptr, N_PEP, cp, nullptr, 0,
                 nullptr, nullptr);
    cudaEventRecord(eCp, s2);

    // ---- s1: mhc branch (fp16 agg sources; l2pm fused with cm) ----
    conv_h_kernel<<<divup(N_MHC * EMB, 256), 256, 0, s1>>>(emb_mhc, embmhc_s, N_MHC * EMB);
    cudaEventRecord(eEmbMhc, s1);
    cudaStreamWaitEvent(s1, ePm, 0);
    cudaStreamWaitEvent(s1, eEmbPep, 0);
    agg_h_kernel<EMB><<<divup(N_MHC, 8), 256, 0, s1>>>(head_pm, next_pm, src_pm, embpep_s,
                                                       mean_pm_s, N_MHC);
    cudaStreamWaitEvent(s1, eWconv, 0);
    launch_mma_s(s1, mean_pm_s, EMB, w_l1pmWl, embmhc_s, EMB, w_l1pmWr, l1_pm_bl,
                 nullptr, N_MHC, nullptr, mhc1_s, 1, nullptr, nullptr);
    cudaEventRecord(eMhc1, s1);
    launch_mma_s(s1, mean_pm_s, EMB, w_l2pmWl, mhc1_s, HID, w_l2pmWr, l2_pm_bl,
                 nullptr, N_MHC, nullptr, nullptr, 1, w_W1m, cm);
    cudaEventRecord(eCm, s1);

    // ---- s3: layer-2 tcr aggregation (reads fp16 mhc1_s) ----
    cudaStreamWaitEvent(s3, eMhc1, 0);
    cudaStreamWaitEvent(s3, eTopo, 0);
    agg_h_compact_kernel<HID><<<divup(MAXD, 8), 256, 0, s3>>>(head_mt, next_mt, src_mt, mhc1_s,
                                                              mean_mt2c_s, list, cnt);
    cudaEventRecord(eMt2, s3);

    // ---- s0: tcr critical path (fp16 agg source; l2mt fused with ct) ----
    cudaStreamWaitEvent(s0, eEmbMhc, 0);
    agg_h_compact_kernel<EMB><<<divup(MAXD, 8), 256, 0, s0>>>(head_mt, next_mt, src_mt, embmhc_s,
                                                              mean_mt1c_s, list, cnt);
    cudaStreamWaitEvent(s0, eWconv, 0);
    cudaStreamWaitEvent(s0, eEtcr, 0);
    launch_mma_s(s0, mean_mt1c_s, EMB, w_l1mtWl, etcrc_s, EMB, w_l1mtWr, l1_mt_bl,
                 cnt, MAXD, nullptr, tcr1c_s, 1, nullptr, nullptr);
    cudaStreamWaitEvent(s0, eMt2, 0);
    launch_mma_s(s0, mean_mt2c_s, HID, w_l2mtWl, tcr1c_s, HID, w_l2mtWr, l2_mt_bl,
                 cnt, MAXD, nullptr, nullptr, 1, w_W1t, ctc);

    // ---- join + final ----
    cudaStreamWaitEvent(s0, eCp, 0);
    cudaStreamWaitEvent(s0, eCm, 0);
    final_kernel<<<divup(BATCH, 8), 256, 0, s0>>>(pack_pep, pack_mhc, pack_tcr, map, cp, cm, ctc,
                                                  head_W2, head_b2, out, BATCH);
}

// round 13
// speedup vs baseline: 1.0593x; 1.0593x over previous
#include <cuda_runtime.h>
#include <cuda_fp16.h>
#include <cstdint>

#define N_PEP 20000
#define N_MHC 5000
#define N_TCR 100000
#define EMB 128
#define HID 256
#define E_PM 200000
#define E_MT 400000
#define BATCH 50000
#define MAXD 50000

typedef __half h16;

// ---------------- scratch (device globals) ----------------
__device__ h16 g_mean_pm_s[N_MHC * EMB];
__device__ h16 g_mean_mt1c_s[MAXD * EMB];
__device__ h16 g_mean_mt2c_s[MAXD * HID];
__device__ h16 g_embmhc_s[N_MHC * EMB];
__device__ h16 g_embpep_s[N_PEP * EMB];
__device__ h16 g_etcrc_s[MAXD * EMB];
__device__ h16 g_mhc1_s[N_MHC * HID];
__device__ h16 g_tcr1c_s[MAXD * HID];
__device__ h16 g_wsplit[11][256 * 2 * 256];
__device__ float g_mhc1[N_MHC * HID];
__device__ float g_cp[N_PEP * HID];
__device__ float g_cm[N_MHC * HID];
__device__ float g_ctc[MAXD * HID];
__device__ float g_Mp[HID * EMB];
__device__ float g_bp[HID];
__device__ int g_map[N_TCR];
__device__ int g_list[MAXD];
__device__ int g_cnt[1];
__device__ int g_head_pm[N_MHC];
__device__ int g_next_pm[E_PM];
__device__ int g_head_mt[N_TCR];
__device__ int g_next_mt[E_MT];

static inline int divup(int a, int b) { return (a + b - 1) / b; }

__device__ __forceinline__ uint32_t smem_u32(const void* p) {
    uint32_t a;
    asm("{ .reg .u64 t; cvta.to.shared.u64 t, %1; cvt.u32.u64 %0, t; }" : "=r"(a) : "l"(p));
    return a;
}
__device__ __forceinline__ void cp16(uint32_t dst, const void* src, bool pred) {
    int sz = pred ? 16 : 0;
    asm volatile("cp.async.cg.shared.global [%0], [%1], 16, %2;"
                 :: "r"(dst), "l"(src), "r"(sz) : "memory");
}
__device__ __forceinline__ void split2h(float x, h16& hi, h16& lo) {
    hi = __float2half(x);
    lo = __float2half(x - __half2float(hi));
}

// ---------------- topology kernels ----------------
__global__ void init_kernel(int* head_pm, int* head_mt, int* map, int* cnt) {
    int i = blockIdx.x * blockDim.x + threadIdx.x;
    if (i == 0) cnt[0] = 0;
    if (i < N_MHC) head_pm[i] = -1;
    if (i < N_TCR) { head_mt[i] = -1; map[i] = -1; }
}
// fused: pm edge-list build + mt edge-list build + pack_tcr mark (all independent after init)
__global__ void build_all_kernel(const int* __restrict__ dst_pm, int* head_pm, int* next_pm,
                                 const int* __restrict__ dst_mt, int* head_mt, int* next_mt,
                                 const int* __restrict__ pack, int* map) {
    int e = blockIdx.x * blockDim.x + threadIdx.x;
    if (e < E_PM) next_pm[e] = atomicExch(&head_pm[__ldg(&dst_pm[e])], e);
    if (e < E_MT) next_mt[e] = atomicExch(&head_mt[__ldg(&dst_mt[e])], e);
    if (e < BATCH) map[__ldg(&pack[e])] = -2;
}
__global__ void compact_kernel(int* map, int* list, int* cnt) {
    int i = blockIdx.x * blockDim.x + threadIdx.x;
    if (i < N_TCR && map[i] == -2) {
        int idx = atomicAdd(cnt, 1);
        list[idx] = i;
        map[i] = idx;
    }
}

// ---------------- mean aggregation (fp32 features) -> fp16 output ----------------
template <int K>
__global__ void agg_h_kernel(const int* __restrict__ head, const int* __restrict__ next,
                             const int* __restrict__ srcArr, const float* __restrict__ feat,
                             h16* __restrict__ outS, int nNodes) {
    int w = (blockIdx.x * blockDim.x + threadIdx.x) >> 5;
    int lane = threadIdx.x & 31;
    if (w >= nNodes) return;
    constexpr int NV = K / 128;
    float4 acc[NV];
#pragma unroll
    for (int v = 0; v < NV; v++) acc[v] = make_float4(0.f, 0.f, 0.f, 0.f);
    int e = head[w];
    int cnt = 0;
    while (e >= 0) {
        int en = __ldg(&next[e]);
        int s = __ldg(&srcArr[e]);
        const float4* fr = (const float4*)(feat + (size_t)s * K);
#pragma unroll
        for (int v = 0; v < NV; v++) {
            float4 f = __ldg(&fr[lane + v * 32]);
            acc[v].x += f.x; acc[v].y += f.y; acc[v].z += f.z; acc[v].w += f.w;
        }
        cnt++;
        e = en;
    }
    float inv = 1.0f / (float)(cnt > 1 ? cnt : 1);
    h16* rp = outS + (size_t)w * K;
#pragma unroll
    for (int v = 0; v < NV; v++) {
        int col = 4 * (lane + v * 32);
        ((__half2*)(rp + col))[0] = __floats2half2_rn(acc[v].x * inv, acc[v].y * inv);
        ((__half2*)(rp + col))[1] = __floats2half2_rn(acc[v].z * inv, acc[v].w * inv);
    }
}

template <int K>
__global__ void agg_h_compact_kernel(const int* __restrict__ head, const int* __restrict__ next,
                                     const int* __restrict__ srcArr, const float* __restrict__ feat,
                                     h16* __restrict__ outS, const int* __restrict__ list,
                                     const int* __restrict__ cntp) {
    int w = (blockIdx.x * blockDim.x + threadIdx.x) >> 5;
    int lane = threadIdx.x & 31;
    if (w >= __ldg(cntp)) return;
    int node = __ldg(&list[w]);
    constexpr int NV = K / 128;
    float4 acc[NV];
#pragma unroll
    for (int v = 0; v < NV; v++) acc[v] = make_float4(0.f, 0.f, 0.f, 0.f);
    int e = head[node];
    int cnt = 0;
    while (e >= 0) {
        int en = __ldg(&next[e]);
        int s = __ldg(&srcArr[e]);
        const float4* fr = (const float4*)(feat + (size_t)s * K);
#pragma unroll
        for (int v = 0; v < NV; v++) {
            float4 f = __ldg(&fr[lane + v * 32]);
            acc[v].x += f.x; acc[v].y += f.y; acc[v].z += f.z; acc[v].w += f.w;
        }
        cnt++;
        e = en;
    }
    float inv = 1.0f / (float)(cnt > 1 ? cnt : 1);
    h16* rp = outS + (size_t)w * K;
#pragma unroll
    for (int v = 0; v < NV; v++) {
        int col = 4 * (lane + v * 32);
        ((__half2*)(rp + col))[0] = __floats2half2_rn(acc[v].x * inv, acc[v].y * inv);
        ((__half2*)(rp + col))[1] = __floats2half2_rn(acc[v].z * inv, acc[v].w * inv);
    }
}

// ---------------- fp32 -> fp16 conversions ----------------
__global__ void conv_h_kernel(const float* __restrict__ src, h16* __restrict__ dst, int n) {
    int i = blockIdx.x * blockDim.x + threadIdx.x;
    if (i < n) dst[i] = __float2half(__ldg(&src[i]));
}

__global__ void gather_conv_h_kernel(const float* __restrict__ src, h16* __restrict__ dst,
                                     const int* __restrict__ list, const int* __restrict__ cntp,
                                     int K) {
    int idx = blockIdx.x * blockDim.x + threadIdx.x;
    int cnt = __ldg(cntp);
    if (idx >= cnt * K) return;
    int r = idx / K, k = idx - r * K;
    int sr = __ldg(&list[r]);
    dst[(size_t)r * K + k] = __float2half(__ldg(&src[(size_t)sr * K + k]));
}

struct WEntry { const float* src; h16* dst; int ld, off, K; };
struct WTable { WEntry e[11]; };
__global__ void wconv_kernel(WTable tab) {
    WEntry w = tab.e[blockIdx.y];
    int idx = blockIdx.x * 256 + threadIdx.x;
    if (idx >= 256 * w.K) return;
    int n = idx / w.K, k = idx - n * w.K;
    h16 hi, lo;
    split2h(__ldg(&w.src[(size_t)n * w.ld + w.off + k]), hi, lo);
    w.dst[((size_t)n * 2) * w.K + k] = hi;
    w.dst[((size_t)n * 2 + 1) * w.K + k] = lo;
}

// ---------------- warp-MMA fp16 GEMM (2-term weight split) + optional fused stage-2 ----------------
#define KC2 32
#define STR2 40
#define YSTR 264
#define SM_Y 0
#define SM_A_OFF(stg)    (67584 + (stg) * 10240)
#define SM_W_OFF(stg, p) (88064 + ((stg) * 2 + (p)) * 20480)
#define SMEM_TOTAL_G (88064 + 81920)

__global__ __launch_bounds__(512) void mma_gemm_kernel(
    const h16* __restrict__ A, int Ka, const h16* __restrict__ Wa,
    const h16* __restrict__ B, int Kb, const h16* __restrict__ Wb,
    const float* __restrict__ bias, const int* __restrict__ rows_ptr, int rows,
    float* __restrict__ Yf, h16* __restrict__ Ys, int do_relu,
    const h16* __restrict__ V, float* __restrict__ Y2f) {
    if (rows_ptr) { int r = __ldg(rows_ptr); if (r < rows) rows = r; }
    const int m0 = blockIdx.x * 128;
    if (m0 >= rows) return;

    extern __shared__ char dynsm[];
    const uint32_t sb = smem_u32(dynsm);

    const int t = threadIdx.x, lane = t & 31, wid = t >> 5;
    const int wm = wid & 1;
    const int wn = wid >> 1;
    const int g = lane >> 2, tg = lane & 3;

    const int a_row = lane & 15;
    const int a_coff = (lane >> 4) << 3;
    const int b_row = lane & 7;
    const int b_coff = ((lane >> 3) & 1) << 3;

    float acc[4][4][4];
#pragma unroll
    for (int i = 0; i < 4; i++)
#pragma unroll
        for (int j = 0; j < 4; j++)
#pragma unroll
            for (int c = 0; c < 4; c++) acc[i][j][c] = 0.f;

    const int nchA = Ka / KC2;
    const int nch = nchA + (B ? Kb / KC2 : 0);

    const int la_row = t >> 2, la_seg = t & 3;
    const bool la_in = (m0 + la_row) < rows;

    auto issue = [&](int c, int stg) {
        const bool isB = (c >= nchA);
        const int k0 = (isB ? c - nchA : c) * KC2;
        const h16* X = isB ? B : A;
        const h16* W = isB ? Wb : Wa;
        const int Kx = isB ? Kb : Ka;
        {
            uint32_t dst = sb + SM_A_OFF(stg) + (la_row * STR2 + la_seg * 8) * 2;
            const h16* src = X + (size_t)(m0 + la_row) * Kx + k0 + la_seg * 8;
            cp16(dst, src, la_in);
        }
#pragma unroll
        for (int p = 0; p < 2; p++) {
#pragma unroll
            for (int rep = 0; rep < 2; rep++) {
                int u = t + rep * 512;
                int wr = u >> 2, ws = u & 3;
                uint32_t dst = sb + SM_W_OFF(stg, p) + (wr * STR2 + ws * 8) * 2;
                const h16* src = W + ((size_t)wr * 2 + p) * Kx + k0 + ws * 8;
                cp16(dst, src, true);
            }
        }
        asm volatile("cp.async.commit_group;" ::: "memory");
    };

    issue(0, 0);
    for (int c = 0; c < nch; c++) {
        const int stg = c & 1;
        if (c + 1 < nch) {
            issue(c + 1, (c + 1) & 1);
            asm volatile("cp.async.wait_group 1;" ::: "memory");
        } else {
            asm volatile("cp.async.wait_group 0;" ::: "memory");
        }
        __syncthreads();

#pragma unroll
        for (int ks = 0; ks < 2; ks++) {
            const int kc = ks * 16;
            uint32_t bh[4][2], bl[4][2];
#pragma unroll
            for (int nt = 0; nt < 4; nt++) {
                int nr = wn * 32 + nt * 8;
                uint32_t off = ((nr + b_row) * STR2 + kc + b_coff) * 2;
                asm volatile("ldmatrix.sync.aligned.m8n8.x2.shared.b16 {%0,%1}, [%2];"
                             : "=r"(bh[nt][0]), "=r"(bh[nt][1])
                             : "r"(sb + SM_W_OFF(stg, 0) + off));
                asm volatile("ldmatrix.sync.aligned.m8n8.x2.shared.b16 {%0,%1}, [%2];"
                             : "=r"(bl[nt][0]), "=r"(bl[nt][1])
                             : "r"(sb + SM_W_OFF(stg, 1) + off));
            }
#pragma unroll
            for (int mt = 0; mt < 4; mt++) {
                int mr = wm * 64 + mt * 16;
                uint32_t ah[4];
                uint32_t pa = sb + SM_A_OFF(stg) + ((mr + a_row) * STR2 + kc + a_coff) * 2;
                asm volatile("ldmatrix.sync.aligned.m8n8.x4.shared.b16 {%0,%1,%2,%3}, [%4];"
                             : "=r"(ah[0]), "=r"(ah[1]), "=r"(ah[2]), "=r"(ah[3]) : "r"(pa));
#pragma unroll
                for (int nt = 0; nt < 4; nt++) {
                    asm volatile(
                        "mma.sync.aligned.m16n8k16.row.col.f32.f16.f16.f32 "
                        "{%0,%1,%2,%3}, {%4,%5,%6,%7}, {%8,%9}, {%0,%1,%2,%3};"
                        : "+f"(acc[mt][nt][0]), "+f"(acc[mt][nt][1]),
                          "+f"(acc[mt][nt][2]), "+f"(acc[mt][nt][3])
                        : "r"(ah[0]), "r"(ah[1]), "r"(ah[2]), "r"(ah[3]),
                          "r"(bh[nt][0]), "r"(bh[nt][1]));
                    asm volatile(
                        "mma.sync.aligned.m16n8k16.row.col.f32.f16.f16.f32 "
                        "{%0,%1,%2,%3}, {%4,%5,%6,%7}, {%8,%9}, {%0,%1,%2,%3};"
                        : "+f"(acc[mt][nt][0]), "+f"(acc[mt][nt][1]),
                          "+f"(acc[mt][nt][2]), "+f"(acc[mt][nt][3])
                        : "r"(ah[0]), "r"(ah[1]), "r"(ah[2]), "r"(ah[3]),
                          "r"(bl[nt][0]), "r"(bl[nt][1]));
                }
            }
        }
        __syncthreads();
    }

    if (!V) {
#pragma unroll
        for (int mt = 0; mt < 4; mt++) {
            int r0 = m0 + wm * 64 + mt * 16 + g;
#pragma unroll
            for (int half = 0; half < 2; half++) {
                int row = r0 + half * 8;
                if (row >= rows) continue;
#pragma unroll
                for (int nt = 0; nt < 4; nt++) {
                    int col = wn * 32 + nt * 8 + tg * 2;
                    float v0 = acc[mt][nt][half * 2 + 0];
                    float v1 = acc[mt][nt][half * 2 + 1];
                    if (bias) { v0 += __ldg(&bias[col]); v1 += __ldg(&bias[col + 1]); }
                    if (do_relu) { v0 = fmaxf(v0, 0.f); v1 = fmaxf(v1, 0.f); }
                    if (Yf) *(float2*)(Yf + (size_t)row * HID + col) = make_float2(v0, v1);
                    if (Ys) *(__half2*)(Ys + (size_t)row * HID + col) = __floats2half2_rn(v0, v1);
                }
            }
        }
        return;
    }

    // ---- fused stage 2: Y2 = T @ V^T ----
    auto issueV = [&](int c, int stg) {
        const int k0 = c * KC2;
#pragma unroll
        for (int p = 0; p < 2; p++) {
#pragma unroll
            for (int rep = 0; rep < 2; rep++) {
                int u = t + rep * 512;
                int wr = u >> 2, ws = u & 3;
                uint32_t dst = sb + SM_W_OFF(stg, p) + (wr * STR2 + ws * 8) * 2;
                const h16* src = V + ((size_t)wr * 2 + p) * HID + k0 + ws * 8;
                cp16(dst, src, true);
            }
        }
        asm volatile("cp.async.commit_group;" ::: "memory");
    };

    issueV(0, 0);

#pragma unroll
    for (int mt = 0; mt < 4; mt++) {
        int lr0 = wm * 64 + mt * 16 + g;
#pragma unroll
        for (int half = 0; half < 2; half++) {
            int lrow = lr0 + half * 8;
#pragma unroll
            for (int nt = 0; nt < 4; nt++) {
                int col = wn * 32 + nt * 8 + tg * 2;
                float v0 = acc[mt][nt][half * 2 + 0];
                float v1 = acc[mt][nt][half * 2 + 1];
                if (bias) { v0 += __ldg(&bias[col]); v1 += __ldg(&bias[col + 1]); }
                if (do_relu) { v0 = fmaxf(v0, 0.f); v1 = fmaxf(v1, 0.f); }
                *(__half2*)(dynsm + SM_Y + (lrow * YSTR + col) * 2) = __floats2half2_rn(v0, v1);
            }
        }
    }

#pragma unroll
    for (int i = 0; i < 4; i++)
#pragma unroll
        for (int j = 0; j < 4; j++)
#pragma unroll
            for (int c = 0; c < 4; c++) acc[i][j][c] = 0.f;

    const int nch2 = HID / KC2;  // 8
    __syncthreads();
    for (int c = 0; c < nch2; c++) {
        const int stg = c & 1;
        if (c + 1 < nch2) {
            issueV(c + 1, (c + 1) & 1);
            asm volatile("cp.async.wait_group 1;" ::: "memory");
        } else {
            asm volatile("cp.async.wait_group 0;" ::: "memory");
        }
        __syncthreads();
        const int k0 = c * KC2;

#pragma unroll
        for (int ks = 0; ks < 2; ks++) {
            const int kc = ks * 16;
            uint32_t bh[4][2], bl[4][2];
#pragma unroll
            for (int nt = 0; nt < 4; nt++) {
                int nr = wn * 32 + nt * 8;
                uint32_t off = ((nr + b_row) * STR2 + kc + b_coff) * 2;
                asm volatile("ldmatrix.sync.aligned.m8n8.x2.shared.b16 {%0,%1}, [%2];"
                             : "=r"(bh[nt][0]), "=r"(bh[nt][1])
                             : "r"(sb + SM_W_OFF(stg, 0) + off));
                asm volatile("ldmatrix.sync.aligned.m8n8.x2.shared.b16 {%0,%1}, [%2];"
                             : "=r"(bl[nt][0]), "=r"(bl[nt][1])
                             : "r"(sb + SM_W_OFF(stg, 1) + off));
            }
#pragma unroll
            for (int mt = 0; mt < 4; mt++) {
                int mr = wm * 64 + mt * 16;
                uint32_t ah[4];
                uint32_t pa = sb + SM_Y + ((mr + a_row) * YSTR + k0 + kc + a_coff) * 2;
                asm volatile("ldmatrix.sync.aligned.m8n8.x4.shared.b16 {%0,%1,%2,%3}, [%4];"
                             : "=r"(ah[0]), "=r"(ah[1]), "=r"(ah[2]), "=r"(ah[3]) : "r"(pa));
#pragma unroll
                for (int nt = 0; nt < 4; nt++) {
                    asm volatile(
                        "mma.sync.aligned.m16n8k16.row.col.f32.f16.f16.f32 "
                        "{%0,%1,%2,%3}, {%4,%5,%6,%7}, {%8,%9}, {%0,%1,%2,%3};"
                        : "+f"(acc[mt][nt][0]), "+f"(acc[mt][nt][1]),
                          "+f"(acc[mt][nt][2]), "+f"(acc[mt][nt][3])
                        : "r"(ah[0]), "r"(ah[1]), "r"(ah[2]), "r"(ah[3]),
                          "r"(bh[nt][0]), "r"(bh[nt][1]));
                    asm volatile(
                        "mma.sync.aligned.m16n8k16.row.col.f32.f16.f16.f32 "
                        "{%0,%1,%2,%3}, {%4,%5,%6,%7}, {%8,%9}, {%0,%1,%2,%3};"
                        : "+f"(acc[mt][nt][0]), "+f"(acc[mt][nt][1]),
                          "+f"(acc[mt][nt][2]), "+f"(acc[mt][nt][3])
                        : "r"(ah[0]), "r"(ah[1]), "r"(ah[2]), "r"(ah[3]),
                          "r"(bl[nt][0]), "r"(bl[nt][1]));
                }
            }
        }
        __syncthreads();
    }

#pragma unroll
    for (int mt = 0; mt < 4; mt++) {
        int r0 = m0 + wm * 64 + mt * 16 + g;
#pragma unroll
        for (int half = 0; half < 2; half++) {
            int row = r0 + half * 8;
            if (row >= rows) continue;
#pragma unroll
            for (int nt = 0; nt < 4; nt++) {
                int col = wn * 32 + nt * 8 + tg * 2;
                *(float2*)(Y2f + (size_t)row * HID + col) =
                    make_float2(acc[mt][nt][half * 2 + 0], acc[mt][nt][half * 2 + 1]);
            }
        }
    }
}

// ---------------- head folding precompute ----------------
__global__ void prep_head_kernel(const float* __restrict__ head_W1, const float* __restrict__ head_b1,
                                 const float* __restrict__ proj_W, const float* __restrict__ proj_b,
                                 float* __restrict__ Mp, float* __restrict__ bp) {
    int n = blockIdx.x;
    int k = threadIdx.x;
    float acc = 0.f;
    for (int j = 0; j < HID; j++) {
        float w = __ldg(&head_W1[n * (3 * HID) + j]);
        acc = fmaf(w, __ldg(&proj_W[j * EMB + k]), acc);
    }
    Mp[n * EMB + k] = acc;
    float pb = __ldg(&head_W1[n * (3 * HID) + k]) * __ldg(&proj_b[k]) +
               __ldg(&head_W1[n * (3 * HID) + k + 128]) * __ldg(&proj_b[k + 128]);
    __shared__ float s[128];
    s[k] = pb;
    __syncthreads();
    for (int st = 64; st > 0; st >>= 1) {
        if (k < st) s[k] += s[k + st];
        __syncthreads();
    }
    if (k == 0) bp[n] = s[0] + head_b1[n];
}

// ---------------- final ----------------
__global__ void final_kernel(const int* __restrict__ pp, const int* __restrict__ pm,
                             const int* __restrict__ pt, const int* __restrict__ map,
                             const float* __restrict__ cp, const float* __restrict__ cm,
                             const float* __restrict__ ctc, const float* __restrict__ w2,
                             const float* __restrict__ b2, float* __restrict__ out, int Bn) {
    int w = (blockIdx.x * blockDim.x + threadIdx.x) >> 5;
    int lane = threadIdx.x & 31;
    if (w >= Bn) return;
    int ip = __ldg(&pp[w]);
    int im = __ldg(&pm[w]);
    int it = __ldg(&map[__ldg(&pt[w])]);
    const float4* rp = (const float4*)(cp + (size_t)ip * HID);
    const float4* rm = (const float4*)(cm + (size_t)im * HID);
    const float4* rt = (const float4*)(ctc + (size_t)it * HID);
    const float4* rw = (const float4*)w2;
    float sum = 0.f;
#pragma unroll
    for (int v = 0; v < 2; v++) {
        float4 a = __ldg(&rp[lane + v * 32]);
        float4 b = __ldg(&rm[lane + v * 32]);
        float4 c = __ldg(&rt[lane + v * 32]);
        float4 ww = __ldg(&rw[lane + v * 32]);
        sum = fmaf(fmaxf(a.x + b.x + c.x, 0.f), ww.x, sum);
        sum = fmaf(fmaxf(a.y + b.y + c.y, 0.f), ww.y, sum);
        sum = fmaf(fmaxf(a.z + b.z + c.z, 0.f), ww.z, sum);
        sum = fmaf(fmaxf(a.w + b.w + c.w, 0.f), ww.w, sum);
    }
#pragma unroll
    for (int o = 16; o > 0; o >>= 1) sum += __shfl_xor_sync(0xFFFFFFFFu, sum, o);
    if (lane == 0) out[w] = sum + b2[0];
}

// ---------------- launch ----------------
static void launch_mma_s(cudaStream_t st, const h16* A, int Ka, const h16* Wa, const h16* B,
                         int Kb, const h16* Wb, const float* bias, const int* rows_ptr, int rows,
                         float* Yf, h16* Ys, int relu, const h16* V, float* Y2f) {
    mma_gemm_kernel<<<divup(rows, 128), 512, SMEM_TOTAL_G, st>>>(A, Ka, Wa, B, Kb, Wb, bias,
                                                                 rows_ptr, rows, Yf, Ys, relu,
                                                                 V, Y2f);
}

extern "C" void kernel_launch(void* const* d_in, const int* in_sizes, int n_in,
                              void* d_out, int out_size) {
    const float* emb_pep = (const float*)d_in[0];
    const float* emb_mhc = (const float*)d_in[1];
    const float* emb_tcr = (const float*)d_in[2];
    const int* src_pm = (const int*)d_in[3];
    const int* dst_pm = (const int*)d_in[4];
    const int* src_mt = (const int*)d_in[5];
    const int* dst_mt = (const int*)d_in[6];
    const int* pack_pep = (const int*)d_in[7];
    const int* pack_mhc = (const int*)d_in[8];
    const int* pack_tcr = (const int*)d_in[9];
    const float* l1_pm_Wl = (const float*)d_in[10];
    const float* l1_pm_bl = (const float*)d_in[11];
    const float* l1_pm_Wr = (const float*)d_in[12];
    const float* l1_mt_Wl = (const float*)d_in[13];
    const float* l1_mt_bl = (const float*)d_in[14];
    const float* l1_mt_Wr = (const float*)d_in[15];
    const float* l2_pm_Wl = (const float*)d_in[16];
    const float* l2_pm_bl = (const float*)d_in[17];
    const float* l2_pm_Wr = (const float*)d_in[18];
    const float* l2_mt_Wl = (const float*)d_in[19];
    const float* l2_mt_bl = (const float*)d_in[20];
    const float* l2_mt_Wr = (const float*)d_in[21];
    const float* proj_W = (const float*)d_in[22];
    const float* proj_b = (const float*)d_in[23];
    const float* head_W1 = (const float*)d_in[24];
    const float* head_b1 = (const float*)d_in[25];
    const float* head_W2 = (const float*)d_in[26];
    const float* head_b2 = (const float*)d_in[27];
    float* out = (float*)d_out;

    static cudaStream_t s1 = 0, s2 = 0, s3 = 0;
    static cudaEvent_t eBegin, eTopo, eWconv, eEtcr, eMhc1, eMt2, eCm, eCp;
    static bool inited = false;
    if (!inited) {
        cudaFuncSetAttribute(mma_gemm_kernel, cudaFuncAttributeMaxDynamicSharedMemorySize,
                             SMEM_TOTAL_G);
        cudaStreamCreateWithFlags(&s1, cudaStreamNonBlocking);
        cudaStreamCreateWithFlags(&s2, cudaStreamNonBlocking);
        cudaStreamCreateWithFlags(&s3, cudaStreamNonBlocking);
        cudaEventCreateWithFlags(&eBegin, cudaEventDisableTiming);
        cudaEventCreateWithFlags(&eTopo, cudaEventDisableTiming);
        cudaEventCreateWithFlags(&eWconv, cudaEventDisableTiming);
        cudaEventCreateWithFlags(&eEtcr, cudaEventDisableTiming);
        cudaEventCreateWithFlags(&eMhc1, cudaEventDisableTiming);
        cudaEventCreateWithFlags(&eMt2, cudaEventDisableTiming);
        cudaEventCreateWithFlags(&eCm, cudaEventDisableTiming);
        cudaEventCreateWithFlags(&eCp, cudaEventDisableTiming);
        inited = true;
    }
    cudaStream_t s0 = 0;

    h16 *mean_pm_s, *mean_mt1c_s, *mean_mt2c_s, *embmhc_s, *embpep_s, *etcrc_s;
    h16 *mhc1_s, *tcr1c_s, *wsplit;
    float *mhc1, *cp, *cm, *ctc, *Mp, *bp;
    int *map, *list, *cnt, *head_pm, *next_pm, *head_mt, *next_mt;
    cudaGetSymbolAddress((void**)&mean_pm_s, g_mean_pm_s);
    cudaGetSymbolAddress((void**)&mean_mt1c_s, g_mean_mt1c_s);
    cudaGetSymbolAddress((void**)&mean_mt2c_s, g_mean_mt2c_s);
    cudaGetSymbolAddress((void**)&embmhc_s, g_embmhc_s);
    cudaGetSymbolAddress((void**)&embpep_s, g_embpep_s);
    cudaGetSymbolAddress((void**)&etcrc_s, g_etcrc_s);
    cudaGetSymbolAddress((void**)&mhc1_s, g_mhc1_s);
    cudaGetSymbolAddress((void**)&tcr1c_s, g_tcr1c_s);
    cudaGetSymbolAddress((void**)&wsplit, g_wsplit);
    cudaGetSymbolAddress((void**)&mhc1, g_mhc1);
    cudaGetSymbolAddress((void**)&cp, g_cp);
    cudaGetSymbolAddress((void**)&cm, g_cm);
    cudaGetSymbolAddress((void**)&ctc, g_ctc);
    cudaGetSymbolAddress((void**)&Mp, g_Mp);
    cudaGetSymbolAddress((void**)&bp, g_bp);
    cudaGetSymbolAddress((void**)&map, g_map);
    cudaGetSymbolAddress((void**)&list, g_list);
    cudaGetSymbolAddress((void**)&cnt, g_cnt);
    cudaGetSymbolAddress((void**)&head_pm, g_head_pm);
    cudaGetSymbolAddress((void**)&next_pm, g_next_pm);
    cudaGetSymbolAddress((void**)&head_mt, g_head_mt);
    cudaGetSymbolAddress((void**)&next_mt, g_next_mt);

    const int WSLOT = 256 * 2 * 256;
    h16* w_l1pmWl = wsplit + 0 * WSLOT;
    h16* w_l1pmWr = wsplit + 1 * WSLOT;
    h16* w_l1mtWl = wsplit + 2 * WSLOT;
    h16* w_l1mtWr = wsplit + 3 * WSLOT;
    h16* w_l2pmWl = wsplit + 4 * WSLOT;
    h16* w_l2pmWr = wsplit + 5 * WSLOT;
    h16* w_l2mtWl = wsplit + 6 * WSLOT;
    h16* w_l2mtWr = wsplit + 7 * WSLOT;
    h16* w_Mp     = wsplit + 8 * WSLOT;
    h16* w_W1m    = wsplit + 9 * WSLOT;
    h16* w_W1t    = wsplit + 10 * WSLOT;

    // ---- fork ----
    cudaEventRecord(eBegin, s0);
    cudaStreamWaitEvent(s1, eBegin, 0);
    cudaStreamWaitEvent(s2, eBegin, 0);
    cudaStreamWaitEvent(s3, eBegin, 0);

    // ---- s0: topology (fused builds) ----
    init_kernel<<<divup(N_TCR, 256), 256, 0, s0>>>(head_pm, head_mt, map, cnt);
    build_all_kernel<<<divup(E_MT, 256), 256, 0, s0>>>(dst_pm, head_pm, next_pm,
                                                       dst_mt, head_mt, next_mt,
                                                       pack_tcr, map);
    compact_kernel<<<divup(N_TCR, 256), 256, 0, s0>>>(map, list, cnt);
    cudaEventRecord(eTopo, s0);

    // ---- s2: weights + pep branch ----
    prep_head_kernel<<<HID, 128, 0, s2>>>(head_W1, head_b1, proj_W, proj_b, Mp, bp);
    {
        WTable tab;
        tab.e[0] = {l1_pm_Wl, w_l1pmWl, EMB, 0, EMB};
        tab.e[1] = {l1_pm_Wr, w_l1pmWr, EMB, 0, EMB};
        tab.e[2] = {l1_mt_Wl, w_l1mtWl, EMB, 0, EMB};
        tab.e[3] = {l1_mt_Wr, w_l1mtWr, EMB, 0, EMB};
        tab.e[4] = {l2_pm_Wl, w_l2pmWl, EMB, 0, EMB};
        tab.e[5] = {l2_pm_Wr, w_l2pmWr, HID, 0, HID};
        tab.e[6] = {l2_mt_Wl, w_l2mtWl, HID, 0, HID};
        tab.e[7] = {l2_mt_Wr, w_l2mtWr, HID, 0, HID};
        tab.e[8] = {Mp, w_Mp, EMB, 0, EMB};
        tab.e[9] = {head_W1, w_W1m, 3 * HID, HID, HID};
        tab.e[10] = {head_W1, w_W1t, 3 * HID, 2 * HID, HID};
        wconv_kernel<<<dim3(256, 11), 256, 0, s2>>>(tab);
    }
    cudaEventRecord(eWconv, s2);
    conv_h_kernel<<<divup(N_PEP * EMB, 256), 256, 0, s2>>>(emb_pep, embpep_s, N_PEP * EMB);
    cudaStreamWaitEvent(s2, eTopo, 0);
    gather_conv_h_kernel<<<divup(MAXD * EMB, 256), 256, 0, s2>>>(emb_tcr, etcrc_s, list, cnt, EMB);
    cudaEventRecord(eEtcr, s2);
    launch_mma_s(s2, embpep_s, EMB, w_Mp, nullptr, 0, nullptr, bp, nullptr, N_PEP, cp, nullptr, 0,
                 nullptr, nullptr);
    cudaEventRecord(eCp, s2);

    // ---- s1: mhc branch (l2pm fused with cm) ----
    conv_h_kernel<<<divup(N_MHC * EMB, 256), 256, 0, s1>>>(emb_mhc, embmhc_s, N_MHC * EMB);
    cudaStreamWaitEvent(s1, eTopo, 0);
    agg_h_kernel<EMB><<<divup(N_MHC, 8), 256, 0, s1>>>(head_pm, next_pm, src_pm, emb_pep,
                                                       mean_pm_s, N_MHC);
    cudaStreamWaitEvent(s1, eWconv, 0);
    launch_mma_s(s1, mean_pm_s, EMB, w_l1pmWl, embmhc_s, EMB, w_l1pmWr, l1_pm_bl,
                 nullptr, N_MHC, mhc1, mhc1_s, 1, nullptr, nullptr);
    cudaEventRecord(eMhc1, s1);
    launch_mma_s(s1, mean_pm_s, EMB, w_l2pmWl, mhc1_s, HID, w_l2pmWr, l2_pm_bl,
                 nullptr, N_MHC, nullptr, nullptr, 1, w_W1m, cm);
    cudaEventRecord(eCm, s1);

    // ---- s3: layer-2 tcr aggregation (reads fp32 mhc1) ----
    cudaStreamWaitEvent(s3, eMhc1, 0);
    cudaStreamWaitEvent(s3, eTopo, 0);
    agg_h_compact_kernel<HID><<<divup(MAXD, 8), 256, 0, s3>>>(head_mt, next_mt, src_mt, mhc1,
                                                              mean_mt2c_s, list, cnt);
    cudaEventRecord(eMt2, s3);

    // ---- s0: tcr critical path (l2mt fused with ct) ----
    agg_h_compact_kernel<EMB><<<divup(MAXD, 8), 256, 0, s0>>>(head_mt, next_mt, src_mt, emb_mhc,
                                                              mean_mt1c_s, list, cnt);
    cudaStreamWaitEvent(s0, eWconv, 0);
    cudaStreamWaitEvent(s0, eEtcr, 0);
    launch_mma_s(s0, mean_mt1c_s, EMB, w_l1mtWl, etcrc_s, EMB, w_l1mtWr, l1_mt_bl,
                 cnt, MAXD, nullptr, tcr1c_s, 1, nullptr, nullptr);
    cudaStreamWaitEvent(s0, eMt2, 0);
    launch_mma_s(s0, mean_mt2c_s, HID, w_l2mtWl, tcr1c_s, HID, w_l2mtWr, l2_mt_bl,
                 cnt, MAXD, nullptr, nullptr, 1, w_W1t, ctc);

    // ---- join + final ----
    cudaStreamWaitEvent(s0, eCp, 0);
    cudaStreamWaitEvent(s0, eCm, 0);
    final_kernel<<<divup(BATCH, 8), 256, 0, s0>>>(pack_pep, pack_mhc, pack_tcr, map, cp, cm, ctc,
                                                  head_W2, head_b2, out, BATCH);
}